// round 12
// baseline (speedup 1.0000x reference)
#include <cuda_runtime.h>
#include <cuda_fp16.h>
#include <cstdint>

// Problem constants
#define SLEN 512
#define BSZ  64
#define ID   512
#define HID  512
#define NG   2048   // 4*H
#define NBLK 128    // total persistent blocks for phase 2
#define NBLKD 64    // per direction

#define HS_STRIDE 72                       // padded batch stride (halves)
#define CHUNK_BYTES (128 * HS_STRIDE * 2)  // one k-quarter = 18432 B

// Scratch (device globals: allocation-free)
static __device__ __half   g_Xg[134217728];             // (D, S, B, 4H) fp16
static __device__ __half   g_Xh[16777216];              // X in fp16
static __device__ __half   g_Wh[2097152];               // W in fp16
static __device__ __half   g_h[2][2][HID][HS_STRIDE];   // padded h state
static __device__ unsigned g_sync[2][9][32];            // [d][group0..7|root8], 128B apart

__device__ __forceinline__ uint32_t smem_u32(const void* p) {
    uint32_t a;
    asm("{ .reg .u64 t; cvta.to.shared.u64 t, %1; cvt.u32.u64 %0, t; }"
        : "=r"(a) : "l"(p));
    return a;
}

// ===========================================================================
// Phase 0: convert X and W to fp16 scratch (linear copy)
// ===========================================================================
#define NX4 4194304u
#define NT4 4718592u

__global__ __launch_bounds__(256) void convert_fp16(const float* __restrict__ X,
                                                    const float* __restrict__ W) {
    uint32_t i = blockIdx.x * 256u + threadIdx.x;
    if (i >= NT4) return;
    const float4 v = (i < NX4) ? ((const float4*)X)[i]
                               : ((const float4*)W)[i - NX4];
    __half2 lo = __floats2half2_rn(v.x, v.y);
    __half2 hi = __floats2half2_rn(v.z, v.w);
    uint2 o = make_uint2(*(uint32_t*)&lo, *(uint32_t*)&hi);
    if (i < NX4) ((uint2*)g_Xh)[i] = o;
    else         ((uint2*)g_Wh)[i - NX4] = o;
}

// ===========================================================================
// Phase 1: Xg[d, r, :] = X[r,:] @ W[d]^T + Wb[d] + Rb[d]   (fp16 out)
// fp16 mma.sync.m16n8k16, cp.async double-buffered fp16 tiles.
// ===========================================================================
#define PSTR 40

__global__ __launch_bounds__(256) void gemm_xw_fp16(const float* __restrict__ Bb) {
    __shared__ __half As[2][128][PSTR];
    __shared__ __half Bs[2][128][PSTR];
    __shared__ float biass[128];

    const int tid  = threadIdx.x;
    const int wid  = tid >> 5, lane = tid & 31;
    const int d    = blockIdx.z;
    const int col0 = blockIdx.x * 128;
    const int row0 = blockIdx.y * 128;
    const __half* Am = g_Xh + (size_t)row0 * ID;
    const __half* Bm = g_Wh + ((size_t)d * NG + col0) * ID;
    __half* C = g_Xg + (size_t)d * SLEN * BSZ * NG;

    if (blockIdx.x == 0 && blockIdx.y == 0 && blockIdx.z == 0 && tid < 18)
        g_sync[tid / 9][tid % 9][0] = 0u;

    if (tid < 128) {
        biass[tid] = Bb[(size_t)d * 4096 + col0 + tid]
                   + Bb[(size_t)d * 4096 + 2048 + col0 + tid];
    }

    const int wm  = (wid & 3) * 32;
    const int wn  = (wid >> 2) * 64;
    const int grp = lane >> 2;
    const int thr = lane & 3;

    const int aM  = lane & 15;
    const int aK8 = (lane >> 4) << 3;

    const int fr0 = tid >> 2, fseg = (tid & 3) * 8;

    float cr[2][8][4];
#pragma unroll
    for (int mt = 0; mt < 2; mt++)
#pragma unroll
        for (int nt = 0; nt < 8; nt++)
#pragma unroll
            for (int q = 0; q < 4; q++) cr[mt][nt][q] = 0.f;

    {
#pragma unroll
        for (int it = 0; it < 2; it++) {
            int r = fr0 + it * 64;
            uint32_t da = smem_u32(&As[0][r][fseg]);
            uint32_t db = smem_u32(&Bs[0][r][fseg]);
            asm volatile("cp.async.cg.shared.global [%0], [%1], 16;"
                         :: "r"(da), "l"(Am + (size_t)r * ID + fseg));
            asm volatile("cp.async.cg.shared.global [%0], [%1], 16;"
                         :: "r"(db), "l"(Bm + (size_t)r * ID + fseg));
        }
        asm volatile("cp.async.commit_group;");
    }

#pragma unroll 1
    for (int c = 0; c < 16; c++) {
        if (c < 15) {
            const int kk = (c + 1) * 32;
            const int nb = (c + 1) & 1;
#pragma unroll
            for (int it = 0; it < 2; it++) {
                int r = fr0 + it * 64;
                uint32_t da = smem_u32(&As[nb][r][fseg]);
                uint32_t db = smem_u32(&Bs[nb][r][fseg]);
                asm volatile("cp.async.cg.shared.global [%0], [%1], 16;"
                             :: "r"(da), "l"(Am + (size_t)r * ID + kk + fseg));
                asm volatile("cp.async.cg.shared.global [%0], [%1], 16;"
                             :: "r"(db), "l"(Bm + (size_t)r * ID + kk + fseg));
            }
            asm volatile("cp.async.commit_group;");
            asm volatile("cp.async.wait_group 1;");
        } else {
            asm volatile("cp.async.wait_group 0;");
        }
        __syncthreads();

        const int cb = c & 1;
#pragma unroll
        for (int ks = 0; ks < 2; ks++) {
            const int k0 = ks * 16;
            uint32_t af[2][4];
#pragma unroll
            for (int mt = 0; mt < 2; mt++) {
                uint32_t addr = smem_u32(&As[cb][wm + mt * 16 + aM][k0 + aK8]);
                asm volatile(
                    "ldmatrix.sync.aligned.m8n8.x4.shared.b16 {%0,%1,%2,%3}, [%4];"
                    : "=r"(af[mt][0]), "=r"(af[mt][1]), "=r"(af[mt][2]), "=r"(af[mt][3])
                    : "r"(addr));
            }
#pragma unroll
            for (int nt16 = 0; nt16 < 4; nt16++) {
                uint32_t r0, r1, r2, r3;
                uint32_t addr = smem_u32(&Bs[cb][wn + nt16 * 16 + aM][k0 + aK8]);
                asm volatile(
                    "ldmatrix.sync.aligned.m8n8.x4.shared.b16 {%0,%1,%2,%3}, [%4];"
                    : "=r"(r0), "=r"(r1), "=r"(r2), "=r"(r3) : "r"(addr));
#pragma unroll
                for (int mt = 0; mt < 2; mt++) {
                    asm volatile(
                        "mma.sync.aligned.m16n8k16.row.col.f32.f16.f16.f32 "
                        "{%0,%1,%2,%3}, {%4,%5,%6,%7}, {%8,%9}, {%0,%1,%2,%3};"
                        : "+f"(cr[mt][2 * nt16][0]), "+f"(cr[mt][2 * nt16][1]),
                          "+f"(cr[mt][2 * nt16][2]), "+f"(cr[mt][2 * nt16][3])
                        : "r"(af[mt][0]), "r"(af[mt][1]), "r"(af[mt][2]), "r"(af[mt][3]),
                          "r"(r0), "r"(r2));
                    asm volatile(
                        "mma.sync.aligned.m16n8k16.row.col.f32.f16.f16.f32 "
                        "{%0,%1,%2,%3}, {%4,%5,%6,%7}, {%8,%9}, {%0,%1,%2,%3};"
                        : "+f"(cr[mt][2 * nt16 + 1][0]), "+f"(cr[mt][2 * nt16 + 1][1]),
                          "+f"(cr[mt][2 * nt16 + 1][2]), "+f"(cr[mt][2 * nt16 + 1][3])
                        : "r"(af[mt][0]), "r"(af[mt][1]), "r"(af[mt][2]), "r"(af[mt][3]),
                          "r"(r1), "r"(r3));
                }
            }
        }
        __syncthreads();
    }

#pragma unroll
    for (int mt = 0; mt < 2; mt++) {
        const int m0 = row0 + wm + mt * 16 + grp;
#pragma unroll
        for (int nt = 0; nt < 8; nt++) {
            const int cl = wn + nt * 8 + 2 * thr;
            __half2 v0 = __floats2half2_rn(cr[mt][nt][0] + biass[cl],
                                           cr[mt][nt][1] + biass[cl + 1]);
            __half2 v1 = __floats2half2_rn(cr[mt][nt][2] + biass[cl],
                                           cr[mt][nt][3] + biass[cl + 1]);
            *(__half2*)(C + (size_t)m0 * NG + col0 + cl)       = v0;
            *(__half2*)(C + (size_t)(m0 + 8) * NG + col0 + cl) = v1;
        }
    }
}

// ===========================================================================
// Phase 2: persistent bidirectional recurrence, fp16 mma.m16n8k16.
// Two-level barrier tree: 8 line-padded group counters + root per direction.
// ===========================================================================
__device__ __forceinline__ void grid_barrier2(unsigned* grpc, unsigned* rootc,
                                              bool leader, unsigned target) {
    __syncthreads();
    if (threadIdx.x == 0) {
        asm volatile("red.release.gpu.global.add.u32 [%0], 1;"
                     :: "l"(grpc) : "memory");
        if (leader) {
            unsigned v;
            do {
                asm volatile("ld.acquire.gpu.u32 %0, [%1];"
                             : "=r"(v) : "l"(grpc) : "memory");
            } while (v < target);
            asm volatile("red.release.gpu.global.add.u32 [%0], 1;"
                         :: "l"(rootc) : "memory");
        }
        unsigned v;
        do {
            asm volatile("ld.acquire.gpu.u32 %0, [%1];"
                         : "=r"(v) : "l"(rootc) : "memory");
        } while (v < target);
    }
    __syncthreads();
}

__device__ __forceinline__ float sigmoidf_(float x) {
    return 1.f / (1.f + __expf(-x));
}
__device__ __forceinline__ float tanhf_(float x) {
    float ax = fabsf(x);
    float e  = __expf(-2.f * ax);
    float r  = (1.f - e) / (1.f + e);
    return copysignf(r, x);
}

#define HS_BYTES  (512 * HS_STRIDE * 2)

__global__ __launch_bounds__(512, 1) void lstm_rec(const float* __restrict__ R,
                                                   const int*   __restrict__ seq,
                                                   const float* __restrict__ h0,
                                                   const float* __restrict__ c0,
                                                   const float* __restrict__ P,
                                                   float* __restrict__ out) {
    extern __shared__ __half hs[];           // [512][HS_STRIDE] fp16 h
    __shared__ float accs[4][4][8][65];      // [kg][gate][hl][b]
    __shared__ float xgs[4][64][9];          // [gate][b][hl]
    __shared__ float cs[8][64], c0s[8][64], h0s[8][64];
    __shared__ float Ps[3][8];
    __shared__ int   slen[BSZ];

    const int blk = blockIdx.x;
    const int d   = blk >> 6;
    const int myj = blk & 63;
    const int hb  = myj * 8;
    const int tid = threadIdx.x;
    const int wid = tid >> 5, lane = tid & 31;
    const int grp = lane >> 2, thr = lane & 3;
    const int mg  = wid & 1;
    const int ng  = (wid >> 1) & 1;
    const int kg  = wid >> 2;
    const int m0  = mg * 32;
    const int kb0 = kg * 128;

    unsigned* grpc  = &g_sync[d][myj >> 3][0];
    unsigned* rootc = &g_sync[d][8][0];
    const bool leader = (myj & 7) == 0;

    const uint32_t hs_b = smem_u32(hs);

    const int seg   = lane >> 3;
    const int laneK = ((seg >> 1) << 3) + (lane & 7);
    const int laneM = (seg & 1) << 3;

    uint32_t Rlo[2][8], Rhi[2][8];
#pragma unroll
    for (int nt2 = 0; nt2 < 2; nt2++) {
        const float* Rrow = R + ((size_t)d * NG + (2 * ng + nt2) * 512 + hb + grp) * HID + kb0;
#pragma unroll
        for (int ks = 0; ks < 8; ks++) {
            const int k = ks * 16;
            __half2 lo = __floats2half2_rn(Rrow[k + 2 * thr], Rrow[k + 2 * thr + 1]);
            __half2 hi = __floats2half2_rn(Rrow[k + 2 * thr + 8], Rrow[k + 2 * thr + 9]);
            Rlo[nt2][ks] = *(uint32_t*)&lo;
            Rhi[nt2][ks] = *(uint32_t*)&hi;
        }
    }

    if (tid < BSZ) slen[tid] = seq[tid];
    if (tid < 24) {
        int w = tid / 8, hl = tid % 8;
        Ps[w][hl] = P[(size_t)d * 1536 + w * 512 + hb + hl];
    }
    {
        int hl = tid >> 6, b = tid & 63;
        size_t idx = ((size_t)d * BSZ + b) * HID + hb + hl;
        float hv = h0[idx], cv = c0[idx];
        h0s[hl][b] = hv; c0s[hl][b] = cv; cs[hl][b] = cv;
        g_h[0][d][hb + hl][b] = __float2half(hv);
    }

    grid_barrier2(grpc, rootc, leader, 8u);   // h0 visible (per dir)

    float* Yh = out + 33554432;
    float* Yc = Yh + 65536;

    const int xb = tid >> 3, xq = tid & 7;
    const int xgate = xq >> 1, xh4 = (xq & 1) * 4;

    const int sgrp   = tid >> 7;
    const int slocal = tid & 127;

    for (int s = 0; s < SLEN; ++s) {
        const int t   = d ? (SLEN - 1 - s) : s;
        const int cur = s & 1, nxt = cur ^ 1;

        // Prefetch this block's Xg tile (fp16) before the barrier
        const __half* xp = g_Xg + (((size_t)d * SLEN + t) * BSZ + xb) * NG
                         + xgate * 512 + hb + xh4;
        uint2 xr = *(const uint2*)xp;

        grid_barrier2(grpc, rootc, leader, 8u * (unsigned)(s + 2));

        {
            float2 lo = __half22float2(*(__half2*)&xr.x);
            float2 hi = __half22float2(*(__half2*)&xr.y);
            xgs[xgate][xb][xh4 + 0] = lo.x;
            xgs[xgate][xb][xh4 + 1] = lo.y;
            xgs[xgate][xb][xh4 + 2] = hi.x;
            xgs[xgate][xb][xh4 + 3] = hi.y;
        }

        // Stage own k-quarter in 2 commit groups
        {
            const char* src = (const char*)&g_h[cur][d][sgrp * 128][0];
            uint32_t    dst = hs_b + (uint32_t)sgrp * CHUNK_BYTES;
#pragma unroll
            for (int i = 0; i < 5; i++) {
                uint32_t off = (uint32_t)(slocal + i * 128) * 16;
                asm volatile("cp.async.cg.shared.global [%0], [%1], 16;"
                             :: "r"(dst + off), "l"(src + off));
            }
            asm volatile("cp.async.commit_group;");
#pragma unroll
            for (int i = 5; i < 9; i++) {
                uint32_t off = (uint32_t)(slocal + i * 128) * 16;
                asm volatile("cp.async.cg.shared.global [%0], [%1], 16;"
                             :: "r"(dst + off), "l"(src + off));
            }
            asm volatile("cp.async.commit_group;");
        }

        float acc[2][2][4];
#pragma unroll
        for (int mtf = 0; mtf < 2; mtf++)
#pragma unroll
            for (int nt2 = 0; nt2 < 2; nt2++)
#pragma unroll
                for (int q = 0; q < 4; q++) acc[mtf][nt2][q] = 0.f;

        asm volatile("cp.async.wait_group 1;");
        asm volatile("bar.sync %0, 128;" :: "r"(1 + sgrp) : "memory");

#pragma unroll
        for (int ks = 0; ks < 4; ks++) {
            const int kb = kb0 + ks * 16 + laneK;
#pragma unroll
            for (int mtf = 0; mtf < 2; mtf++) {
                const int mb = m0 + mtf * 16 + laneM;
                uint32_t addr = hs_b + (uint32_t)(kb * HS_STRIDE + mb) * 2;
                uint32_t a0, a1, a2, a3;
                asm volatile(
                    "ldmatrix.sync.aligned.m8n8.x4.trans.shared.b16 {%0,%1,%2,%3}, [%4];"
                    : "=r"(a0), "=r"(a1), "=r"(a2), "=r"(a3) : "r"(addr));
#pragma unroll
                for (int nt2 = 0; nt2 < 2; nt2++) {
                    asm volatile(
                        "mma.sync.aligned.m16n8k16.row.col.f32.f16.f16.f32 "
                        "{%0,%1,%2,%3}, {%4,%5,%6,%7}, {%8,%9}, {%0,%1,%2,%3};"
                        : "+f"(acc[mtf][nt2][0]), "+f"(acc[mtf][nt2][1]),
                          "+f"(acc[mtf][nt2][2]), "+f"(acc[mtf][nt2][3])
                        : "r"(a0), "r"(a1), "r"(a2), "r"(a3),
                          "r"(Rlo[nt2][ks]), "r"(Rhi[nt2][ks]));
                }
            }
        }

        asm volatile("cp.async.wait_group 0;");
        asm volatile("bar.sync %0, 128;" :: "r"(1 + sgrp) : "memory");

#pragma unroll
        for (int ks = 4; ks < 8; ks++) {
            const int kb = kb0 + ks * 16 + laneK;
#pragma unroll
            for (int mtf = 0; mtf < 2; mtf++) {
                const int mb = m0 + mtf * 16 + laneM;
                uint32_t addr = hs_b + (uint32_t)(kb * HS_STRIDE + mb) * 2;
                uint32_t a0, a1, a2, a3;
                asm volatile(
                    "ldmatrix.sync.aligned.m8n8.x4.trans.shared.b16 {%0,%1,%2,%3}, [%4];"
                    : "=r"(a0), "=r"(a1), "=r"(a2), "=r"(a3) : "r"(addr));
#pragma unroll
                for (int nt2 = 0; nt2 < 2; nt2++) {
                    asm volatile(
                        "mma.sync.aligned.m16n8k16.row.col.f32.f16.f16.f32 "
                        "{%0,%1,%2,%3}, {%4,%5,%6,%7}, {%8,%9}, {%0,%1,%2,%3};"
                        : "+f"(acc[mtf][nt2][0]), "+f"(acc[mtf][nt2][1]),
                          "+f"(acc[mtf][nt2][2]), "+f"(acc[mtf][nt2][3])
                        : "r"(a0), "r"(a1), "r"(a2), "r"(a3),
                          "r"(Rlo[nt2][ks]), "r"(Rhi[nt2][ks]));
                }
            }
        }

#pragma unroll
        for (int mtf = 0; mtf < 2; mtf++) {
            const int m = m0 + mtf * 16 + grp;
#pragma unroll
            for (int nt2 = 0; nt2 < 2; nt2++) {
                const int g = 2 * ng + nt2;
                accs[kg][g][2 * thr]    [m]     = acc[mtf][nt2][0];
                accs[kg][g][2 * thr + 1][m]     = acc[mtf][nt2][1];
                accs[kg][g][2 * thr]    [m + 8] = acc[mtf][nt2][2];
                accs[kg][g][2 * thr + 1][m + 8] = acc[mtf][nt2][3];
            }
        }
        __syncthreads();

        {
            int hl = tid >> 6, b = tid & 63;
            float gi = accs[0][0][hl][b] + accs[1][0][hl][b]
                     + accs[2][0][hl][b] + accs[3][0][hl][b] + xgs[0][b][hl];
            float go = accs[0][1][hl][b] + accs[1][1][hl][b]
                     + accs[2][1][hl][b] + accs[3][1][hl][b] + xgs[1][b][hl];
            float gf = accs[0][2][hl][b] + accs[1][2][hl][b]
                     + accs[2][2][hl][b] + accs[3][2][hl][b] + xgs[2][b][hl];
            float gg = accs[0][3][hl][b] + accs[1][3][hl][b]
                     + accs[2][3][hl][b] + accs[3][3][hl][b] + xgs[3][b][hl];
            float c  = cs[hl][b];
            float iv = sigmoidf_(gi + Ps[0][hl] * c);
            float fv = sigmoidf_(gf + Ps[1][hl] * c);
            float ct = tanhf_(gg);
            float cn = fv * c + iv * ct;
            float ov = sigmoidf_(go + Ps[2][hl] * cn);
            float hn = ov * tanhf_(cn);
            if (t >= slen[b]) { hn = h0s[hl][b]; cn = c0s[hl][b]; }
            cs[hl][b] = cn;
            g_h[nxt][d][hb + hl][b] = __float2half(hn);
            out[(((size_t)t * 2 + d) * BSZ + b) * HID + hb + hl] = hn;
            if (s == SLEN - 1) {
                size_t fi = ((size_t)d * BSZ + b) * HID + hb + hl;
                Yh[fi] = hn;
                Yc[fi] = cn;
            }
        }
    }
}

// ---------------------------------------------------------------------------
extern "C" void kernel_launch(void* const* d_in, const int* in_sizes, int n_in,
                              void* d_out, int out_size) {
    const float* X   = (const float*)d_in[0];
    const float* W   = (const float*)d_in[1];
    const float* R   = (const float*)d_in[2];
    const float* Bb  = (const float*)d_in[3];
    const int*   sl  = (const int*)  d_in[4];
    const float* h0  = (const float*)d_in[5];
    const float* c0  = (const float*)d_in[6];
    const float* P   = (const float*)d_in[7];
    float* out = (float*)d_out;

    static int configured = 0;
    if (!configured) {
        cudaFuncSetAttribute(lstm_rec, cudaFuncAttributeMaxDynamicSharedMemorySize,
                             HS_BYTES);
        configured = 1;
    }

    convert_fp16<<<(NT4 + 255) / 256, 256>>>(X, W);
    gemm_xw_fp16<<<dim3(16, 256, 2), 256>>>(Bb);
    lstm_rec<<<NBLK, 512, HS_BYTES>>>(R, sl, h0, c0, P, out);
}

// round 16
// speedup vs baseline: 1.1745x; 1.1745x over previous
#include <cuda_runtime.h>
#include <cuda_fp16.h>
#include <cstdint>

// Problem constants
#define SLEN 512
#define BSZ  64
#define ID   512
#define HID  512
#define NG   2048   // 4*H
#define NBLK 128    // total persistent blocks for phase 2
#define NBLKD 64    // per direction

#define HS_STRIDE 72                       // padded batch stride (halves)
#define CHUNK_BYTES (128 * HS_STRIDE * 2)  // one k-quarter = 18432 B

// Scratch (device globals: allocation-free)
static __device__ __half   g_Xg[134217728];             // (D, S, B, 4H) fp16
static __device__ __half   g_Xh[16777216];              // X in fp16
static __device__ __half   g_Wh[2097152];               // W in fp16
static __device__ __half   g_h[2][2][HID][HS_STRIDE];   // padded h state
static __device__ unsigned g_barD[2][32];               // per-dir counters, 128B apart

__device__ __forceinline__ uint32_t smem_u32(const void* p) {
    uint32_t a;
    asm("{ .reg .u64 t; cvta.to.shared.u64 t, %1; cvt.u32.u64 %0, t; }"
        : "=r"(a) : "l"(p));
    return a;
}

// ===========================================================================
// Phase 0: convert X and W to fp16 scratch (linear copy)
// ===========================================================================
#define NX4 4194304u
#define NT4 4718592u

__global__ __launch_bounds__(256) void convert_fp16(const float* __restrict__ X,
                                                    const float* __restrict__ W) {
    uint32_t i = blockIdx.x * 256u + threadIdx.x;
    if (i >= NT4) return;
    const float4 v = (i < NX4) ? ((const float4*)X)[i]
                               : ((const float4*)W)[i - NX4];
    __half2 lo = __floats2half2_rn(v.x, v.y);
    __half2 hi = __floats2half2_rn(v.z, v.w);
    uint2 o = make_uint2(*(uint32_t*)&lo, *(uint32_t*)&hi);
    if (i < NX4) ((uint2*)g_Xh)[i] = o;
    else         ((uint2*)g_Wh)[i - NX4] = o;
}

// ===========================================================================
// Phase 1: Xg[d, r, :] = X[r,:] @ W[d]^T + Wb[d] + Rb[d]   (fp16 out)
// fp16 mma.sync.m16n8k16, cp.async double-buffered fp16 tiles.
// ===========================================================================
#define PSTR 40

__global__ __launch_bounds__(256) void gemm_xw_fp16(const float* __restrict__ Bb) {
    __shared__ __half As[2][128][PSTR];
    __shared__ __half Bs[2][128][PSTR];
    __shared__ float biass[128];

    const int tid  = threadIdx.x;
    const int wid  = tid >> 5, lane = tid & 31;
    const int d    = blockIdx.z;
    const int col0 = blockIdx.x * 128;
    const int row0 = blockIdx.y * 128;
    const __half* Am = g_Xh + (size_t)row0 * ID;
    const __half* Bm = g_Wh + ((size_t)d * NG + col0) * ID;
    __half* C = g_Xg + (size_t)d * SLEN * BSZ * NG;

    if (blockIdx.x == 0 && blockIdx.y == 0 && blockIdx.z == 0 && tid < 2)
        g_barD[tid][0] = 0u;

    if (tid < 128) {
        biass[tid] = Bb[(size_t)d * 4096 + col0 + tid]
                   + Bb[(size_t)d * 4096 + 2048 + col0 + tid];
    }

    const int wm  = (wid & 3) * 32;
    const int wn  = (wid >> 2) * 64;
    const int grp = lane >> 2;
    const int thr = lane & 3;

    const int aM  = lane & 15;
    const int aK8 = (lane >> 4) << 3;

    const int fr0 = tid >> 2, fseg = (tid & 3) * 8;

    float cr[2][8][4];
#pragma unroll
    for (int mt = 0; mt < 2; mt++)
#pragma unroll
        for (int nt = 0; nt < 8; nt++)
#pragma unroll
            for (int q = 0; q < 4; q++) cr[mt][nt][q] = 0.f;

    {
#pragma unroll
        for (int it = 0; it < 2; it++) {
            int r = fr0 + it * 64;
            uint32_t da = smem_u32(&As[0][r][fseg]);
            uint32_t db = smem_u32(&Bs[0][r][fseg]);
            asm volatile("cp.async.cg.shared.global [%0], [%1], 16;"
                         :: "r"(da), "l"(Am + (size_t)r * ID + fseg));
            asm volatile("cp.async.cg.shared.global [%0], [%1], 16;"
                         :: "r"(db), "l"(Bm + (size_t)r * ID + fseg));
        }
        asm volatile("cp.async.commit_group;");
    }

#pragma unroll 1
    for (int c = 0; c < 16; c++) {
        if (c < 15) {
            const int kk = (c + 1) * 32;
            const int nb = (c + 1) & 1;
#pragma unroll
            for (int it = 0; it < 2; it++) {
                int r = fr0 + it * 64;
                uint32_t da = smem_u32(&As[nb][r][fseg]);
                uint32_t db = smem_u32(&Bs[nb][r][fseg]);
                asm volatile("cp.async.cg.shared.global [%0], [%1], 16;"
                             :: "r"(da), "l"(Am + (size_t)r * ID + kk + fseg));
                asm volatile("cp.async.cg.shared.global [%0], [%1], 16;"
                             :: "r"(db), "l"(Bm + (size_t)r * ID + kk + fseg));
            }
            asm volatile("cp.async.commit_group;");
            asm volatile("cp.async.wait_group 1;");
        } else {
            asm volatile("cp.async.wait_group 0;");
        }
        __syncthreads();

        const int cb = c & 1;
#pragma unroll
        for (int ks = 0; ks < 2; ks++) {
            const int k0 = ks * 16;
            uint32_t af[2][4];
#pragma unroll
            for (int mt = 0; mt < 2; mt++) {
                uint32_t addr = smem_u32(&As[cb][wm + mt * 16 + aM][k0 + aK8]);
                asm volatile(
                    "ldmatrix.sync.aligned.m8n8.x4.shared.b16 {%0,%1,%2,%3}, [%4];"
                    : "=r"(af[mt][0]), "=r"(af[mt][1]), "=r"(af[mt][2]), "=r"(af[mt][3])
                    : "r"(addr));
            }
#pragma unroll
            for (int nt16 = 0; nt16 < 4; nt16++) {
                uint32_t r0, r1, r2, r3;
                uint32_t addr = smem_u32(&Bs[cb][wn + nt16 * 16 + aM][k0 + aK8]);
                asm volatile(
                    "ldmatrix.sync.aligned.m8n8.x4.shared.b16 {%0,%1,%2,%3}, [%4];"
                    : "=r"(r0), "=r"(r1), "=r"(r2), "=r"(r3) : "r"(addr));
#pragma unroll
                for (int mt = 0; mt < 2; mt++) {
                    asm volatile(
                        "mma.sync.aligned.m16n8k16.row.col.f32.f16.f16.f32 "
                        "{%0,%1,%2,%3}, {%4,%5,%6,%7}, {%8,%9}, {%0,%1,%2,%3};"
                        : "+f"(cr[mt][2 * nt16][0]), "+f"(cr[mt][2 * nt16][1]),
                          "+f"(cr[mt][2 * nt16][2]), "+f"(cr[mt][2 * nt16][3])
                        : "r"(af[mt][0]), "r"(af[mt][1]), "r"(af[mt][2]), "r"(af[mt][3]),
                          "r"(r0), "r"(r2));
                    asm volatile(
                        "mma.sync.aligned.m16n8k16.row.col.f32.f16.f16.f32 "
                        "{%0,%1,%2,%3}, {%4,%5,%6,%7}, {%8,%9}, {%0,%1,%2,%3};"
                        : "+f"(cr[mt][2 * nt16 + 1][0]), "+f"(cr[mt][2 * nt16 + 1][1]),
                          "+f"(cr[mt][2 * nt16 + 1][2]), "+f"(cr[mt][2 * nt16 + 1][3])
                        : "r"(af[mt][0]), "r"(af[mt][1]), "r"(af[mt][2]), "r"(af[mt][3]),
                          "r"(r1), "r"(r3));
                }
            }
        }
        __syncthreads();
    }

#pragma unroll
    for (int mt = 0; mt < 2; mt++) {
        const int m0 = row0 + wm + mt * 16 + grp;
#pragma unroll
        for (int nt = 0; nt < 8; nt++) {
            const int cl = wn + nt * 8 + 2 * thr;
            __half2 v0 = __floats2half2_rn(cr[mt][nt][0] + biass[cl],
                                           cr[mt][nt][1] + biass[cl + 1]);
            __half2 v1 = __floats2half2_rn(cr[mt][nt][2] + biass[cl],
                                           cr[mt][nt][3] + biass[cl + 1]);
            *(__half2*)(C + (size_t)m0 * NG + col0 + cl)       = v0;
            *(__half2*)(C + (size_t)(m0 + 8) * NG + col0 + cl) = v1;
        }
    }
}

// ===========================================================================
// Phase 2: persistent bidirectional recurrence, fp16 mma.m16n8k16.
// Flat per-direction line-padded counter; split arrive (end of step) /
// wait (top of next step).
// ===========================================================================
__device__ __forceinline__ float sigmoidf_(float x) {
    return 1.f / (1.f + __expf(-x));
}
__device__ __forceinline__ float tanhf_(float x) {
    float ax = fabsf(x);
    float e  = __expf(-2.f * ax);
    float r  = (1.f - e) / (1.f + e);
    return copysignf(r, x);
}

#define HS_BYTES  (512 * HS_STRIDE * 2)

__global__ __launch_bounds__(512, 1) void lstm_rec(const float* __restrict__ R,
                                                   const int*   __restrict__ seq,
                                                   const float* __restrict__ h0,
                                                   const float* __restrict__ c0,
                                                   const float* __restrict__ P,
                                                   float* __restrict__ out) {
    extern __shared__ __half hs[];           // [512][HS_STRIDE] fp16 h
    __shared__ float accs[4][4][8][65];      // [kg][gate][hl][b]
    __shared__ float xgs[4][64][9];          // [gate][b][hl]
    __shared__ float cs[8][64], c0s[8][64], h0s[8][64];
    __shared__ float Ps[3][8];
    __shared__ int   slen[BSZ];

    const int blk = blockIdx.x;
    const int d   = blk >> 6;
    const int hb  = (blk & 63) * 8;
    const int tid = threadIdx.x;
    const int wid = tid >> 5, lane = tid & 31;
    const int grp = lane >> 2, thr = lane & 3;
    const int mg  = wid & 1;
    const int ng  = (wid >> 1) & 1;
    const int kg  = wid >> 2;
    const int m0  = mg * 32;
    const int kb0 = kg * 128;

    unsigned* bar = &g_barD[d][0];
    const uint32_t hs_b = smem_u32(hs);

    const int seg   = lane >> 3;
    const int laneK = ((seg >> 1) << 3) + (lane & 7);
    const int laneM = (seg & 1) << 3;

    // ---- publish initial h early, then arrive ----
    if (tid < BSZ) slen[tid] = seq[tid];
    {
        int hl = tid >> 6, b = tid & 63;
        size_t idx = ((size_t)d * BSZ + b) * HID + hb + hl;
        float hv = h0[idx], cv = c0[idx];
        h0s[hl][b] = hv; c0s[hl][b] = cv; cs[hl][b] = cv;
        g_h[0][d][hb + hl][b] = __float2half(hv);
    }
    __syncthreads();
    if (tid == 0)
        asm volatile("red.release.gpu.global.add.u32 [%0], 1;" :: "l"(bar) : "memory");

    // R fragments + peephole preload (overlaps other CTAs' arrivals)
    uint32_t Rlo[2][8], Rhi[2][8];
#pragma unroll
    for (int nt2 = 0; nt2 < 2; nt2++) {
        const float* Rrow = R + ((size_t)d * NG + (2 * ng + nt2) * 512 + hb + grp) * HID + kb0;
#pragma unroll
        for (int ks = 0; ks < 8; ks++) {
            const int k = ks * 16;
            __half2 lo = __floats2half2_rn(Rrow[k + 2 * thr], Rrow[k + 2 * thr + 1]);
            __half2 hi = __floats2half2_rn(Rrow[k + 2 * thr + 8], Rrow[k + 2 * thr + 9]);
            Rlo[nt2][ks] = *(uint32_t*)&lo;
            Rhi[nt2][ks] = *(uint32_t*)&hi;
        }
    }
    if (tid < 24) {
        int w = tid / 8, hl = tid % 8;
        Ps[w][hl] = P[(size_t)d * 1536 + w * 512 + hb + hl];
    }

    float* Yh = out + 33554432;
    float* Yc = Yh + 65536;

    const int xb = tid >> 3, xq = tid & 7;
    const int xgate = xq >> 1, xh4 = (xq & 1) * 4;

    const int sgrp   = tid >> 7;
    const int slocal = tid & 127;

    for (int s = 0; s < SLEN; ++s) {
        const int t   = d ? (SLEN - 1 - s) : s;
        const int cur = s & 1, nxt = cur ^ 1;

        // Prefetch this block's Xg tile (fp16) while waiting
        const __half* xp = g_Xg + (((size_t)d * SLEN + t) * BSZ + xb) * NG
                         + xgate * 512 + hb + xh4;
        uint2 xr = *(const uint2*)xp;

        // Wait: all producers of h(s) have arrived
        if (tid == 0) {
            const unsigned need = (unsigned)NBLKD * (unsigned)(s + 1);
            unsigned v;
            do {
                asm volatile("ld.acquire.gpu.u32 %0, [%1];"
                             : "=r"(v) : "l"(bar) : "memory");
            } while (v < need);
        }
        __syncthreads();

        {
            float2 lo = __half22float2(*(__half2*)&xr.x);
            float2 hi = __half22float2(*(__half2*)&xr.y);
            xgs[xgate][xb][xh4 + 0] = lo.x;
            xgs[xgate][xb][xh4 + 1] = lo.y;
            xgs[xgate][xb][xh4 + 2] = hi.x;
            xgs[xgate][xb][xh4 + 3] = hi.y;
        }

        // Stage own k-quarter in 2 commit groups
        {
            const char* src = (const char*)&g_h[cur][d][sgrp * 128][0];
            uint32_t    dst = hs_b + (uint32_t)sgrp * CHUNK_BYTES;
#pragma unroll
            for (int i = 0; i < 5; i++) {
                uint32_t off = (uint32_t)(slocal + i * 128) * 16;
                asm volatile("cp.async.cg.shared.global [%0], [%1], 16;"
                             :: "r"(dst + off), "l"(src + off));
            }
            asm volatile("cp.async.commit_group;");
#pragma unroll
            for (int i = 5; i < 9; i++) {
                uint32_t off = (uint32_t)(slocal + i * 128) * 16;
                asm volatile("cp.async.cg.shared.global [%0], [%1], 16;"
                             :: "r"(dst + off), "l"(src + off));
            }
            asm volatile("cp.async.commit_group;");
        }

        float acc[2][2][4];
#pragma unroll
        for (int mtf = 0; mtf < 2; mtf++)
#pragma unroll
            for (int nt2 = 0; nt2 < 2; nt2++)
#pragma unroll
                for (int q = 0; q < 4; q++) acc[mtf][nt2][q] = 0.f;

        asm volatile("cp.async.wait_group 1;");
        asm volatile("bar.sync %0, 128;" :: "r"(1 + sgrp) : "memory");

#pragma unroll
        for (int ks = 0; ks < 4; ks++) {
            const int kb = kb0 + ks * 16 + laneK;
#pragma unroll
            for (int mtf = 0; mtf < 2; mtf++) {
                const int mb = m0 + mtf * 16 + laneM;
                uint32_t addr = hs_b + (uint32_t)(kb * HS_STRIDE + mb) * 2;
                uint32_t a0, a1, a2, a3;
                asm volatile(
                    "ldmatrix.sync.aligned.m8n8.x4.trans.shared.b16 {%0,%1,%2,%3}, [%4];"
                    : "=r"(a0), "=r"(a1), "=r"(a2), "=r"(a3) : "r"(addr));
#pragma unroll
                for (int nt2 = 0; nt2 < 2; nt2++) {
                    asm volatile(
                        "mma.sync.aligned.m16n8k16.row.col.f32.f16.f16.f32 "
                        "{%0,%1,%2,%3}, {%4,%5,%6,%7}, {%8,%9}, {%0,%1,%2,%3};"
                        : "+f"(acc[mtf][nt2][0]), "+f"(acc[mtf][nt2][1]),
                          "+f"(acc[mtf][nt2][2]), "+f"(acc[mtf][nt2][3])
                        : "r"(a0), "r"(a1), "r"(a2), "r"(a3),
                          "r"(Rlo[nt2][ks]), "r"(Rhi[nt2][ks]));
                }
            }
        }

        asm volatile("cp.async.wait_group 0;");
        asm volatile("bar.sync %0, 128;" :: "r"(1 + sgrp) : "memory");

#pragma unroll
        for (int ks = 4; ks < 8; ks++) {
            const int kb = kb0 + ks * 16 + laneK;
#pragma unroll
            for (int mtf = 0; mtf < 2; mtf++) {
                const int mb = m0 + mtf * 16 + laneM;
                uint32_t addr = hs_b + (uint32_t)(kb * HS_STRIDE + mb) * 2;
                uint32_t a0, a1, a2, a3;
                asm volatile(
                    "ldmatrix.sync.aligned.m8n8.x4.trans.shared.b16 {%0,%1,%2,%3}, [%4];"
                    : "=r"(a0), "=r"(a1), "=r"(a2), "=r"(a3) : "r"(addr));
#pragma unroll
                for (int nt2 = 0; nt2 < 2; nt2++) {
                    asm volatile(
                        "mma.sync.aligned.m16n8k16.row.col.f32.f16.f16.f32 "
                        "{%0,%1,%2,%3}, {%4,%5,%6,%7}, {%8,%9}, {%0,%1,%2,%3};"
                        : "+f"(acc[mtf][nt2][0]), "+f"(acc[mtf][nt2][1]),
                          "+f"(acc[mtf][nt2][2]), "+f"(acc[mtf][nt2][3])
                        : "r"(a0), "r"(a1), "r"(a2), "r"(a3),
                          "r"(Rlo[nt2][ks]), "r"(Rhi[nt2][ks]));
                }
            }
        }

#pragma unroll
        for (int mtf = 0; mtf < 2; mtf++) {
            const int m = m0 + mtf * 16 + grp;
#pragma unroll
            for (int nt2 = 0; nt2 < 2; nt2++) {
                const int g = 2 * ng + nt2;
                accs[kg][g][2 * thr]    [m]     = acc[mtf][nt2][0];
                accs[kg][g][2 * thr + 1][m]     = acc[mtf][nt2][1];
                accs[kg][g][2 * thr]    [m + 8] = acc[mtf][nt2][2];
                accs[kg][g][2 * thr + 1][m + 8] = acc[mtf][nt2][3];
            }
        }
        __syncthreads();

        {
            int hl = tid >> 6, b = tid & 63;
            float gi = accs[0][0][hl][b] + accs[1][0][hl][b]
                     + accs[2][0][hl][b] + accs[3][0][hl][b] + xgs[0][b][hl];
            float go = accs[0][1][hl][b] + accs[1][1][hl][b]
                     + accs[2][1][hl][b] + accs[3][1][hl][b] + xgs[1][b][hl];
            float gf = accs[0][2][hl][b] + accs[1][2][hl][b]
                     + accs[2][2][hl][b] + accs[3][2][hl][b] + xgs[2][b][hl];
            float gg = accs[0][3][hl][b] + accs[1][3][hl][b]
                     + accs[2][3][hl][b] + accs[3][3][hl][b] + xgs[3][b][hl];
            float c  = cs[hl][b];
            float iv = sigmoidf_(gi + Ps[0][hl] * c);
            float fv = sigmoidf_(gf + Ps[1][hl] * c);
            float ct = tanhf_(gg);
            float cn = fv * c + iv * ct;
            float ov = sigmoidf_(go + Ps[2][hl] * cn);
            float hn = ov * tanhf_(cn);
            if (t >= slen[b]) { hn = h0s[hl][b]; cn = c0s[hl][b]; }
            cs[hl][b] = cn;
            g_h[nxt][d][hb + hl][b] = __float2half(hn);
            out[(((size_t)t * 2 + d) * BSZ + b) * HID + hb + hl] = hn;
            if (s == SLEN - 1) {
                size_t fi = ((size_t)d * BSZ + b) * HID + hb + hl;
                Yh[fi] = hn;
                Yc[fi] = cn;
            }
        }
        __syncthreads();                     // all h(s+1) rows in flight-visible
        if (tid == 0)
            asm volatile("red.release.gpu.global.add.u32 [%0], 1;" :: "l"(bar) : "memory");
    }
}

// ---------------------------------------------------------------------------
extern "C" void kernel_launch(void* const* d_in, const int* in_sizes, int n_in,
                              void* d_out, int out_size) {
    const float* X   = (const float*)d_in[0];
    const float* W   = (const float*)d_in[1];
    const float* R   = (const float*)d_in[2];
    const float* Bb  = (const float*)d_in[3];
    const int*   sl  = (const int*)  d_in[4];
    const float* h0  = (const float*)d_in[5];
    const float* c0  = (const float*)d_in[6];
    const float* P   = (const float*)d_in[7];
    float* out = (float*)d_out;

    static int configured = 0;
    if (!configured) {
        cudaFuncSetAttribute(lstm_rec, cudaFuncAttributeMaxDynamicSharedMemorySize,
                             HS_BYTES);
        configured = 1;
    }

    convert_fp16<<<(NT4 + 255) / 256, 256>>>(X, W);
    gemm_xw_fp16<<<dim3(16, 256, 2), 256>>>(Bb);
    lstm_rec<<<NBLK, 512, HS_BYTES>>>(R, sl, h0, c0, P, out);
}

// round 17
// speedup vs baseline: 1.3254x; 1.1284x over previous
#include <cuda_runtime.h>
#include <cuda_fp16.h>
#include <cstdint>

// Problem constants
#define SLEN 512
#define BSZ  64
#define ID   512
#define HID  512
#define NG   2048   // 4*H
#define NBLK 128
#define NBLKD 64

#define HS_STRIDE 72                       // padded batch stride (halves)
#define CHUNK_BYTES (128 * HS_STRIDE * 2)  // one k-quarter = 18432 B
#define WSTR 520                           // Ws row stride (halves)

// Scratch (device globals: allocation-free)
static __device__ __half   g_Xt[18874368];              // X^T: [t][i][b] padded 72
static __device__ __half   g_Wh[2097152];               // W fp16 (row-major)
static __device__ __half   g_h[2][2][HID][HS_STRIDE];   // padded h state
static __device__ unsigned g_barD[2][32];               // per-dir counters, 128B apart

__device__ __forceinline__ uint32_t smem_u32(const void* p) {
    uint32_t a;
    asm("{ .reg .u64 t; cvta.to.shared.u64 t, %1; cvt.u32.u64 %0, t; }"
        : "=r"(a) : "l"(p));
    return a;
}

// ===========================================================================
// Phase 0a: W -> fp16 (linear). Also resets barriers.
// ===========================================================================
__global__ __launch_bounds__(256) void convert_w(const float* __restrict__ W) {
    uint32_t i = blockIdx.x * 256u + threadIdx.x;
    if (blockIdx.x == 0 && threadIdx.x < 2) g_barD[threadIdx.x][0] = 0u;
    if (i >= 524288u) return;
    float4 v = ((const float4*)W)[i];
    __half2 lo = __floats2half2_rn(v.x, v.y);
    __half2 hi = __floats2half2_rn(v.z, v.w);
    ((uint2*)g_Wh)[i] = make_uint2(*(uint32_t*)&lo, *(uint32_t*)&hi);
}

// ===========================================================================
// Phase 0b: X -> transposed fp16 g_Xt[t][i][b] (stride 72). Block per t.
// ===========================================================================
__global__ __launch_bounds__(256) void convert_xt(const float* __restrict__ X) {
    __shared__ float tile[64][65];
    const int t = blockIdx.x, tid = threadIdx.x;
#pragma unroll 1
    for (int c = 0; c < 8; c++) {
        __syncthreads();
#pragma unroll
        for (int k = 0; k < 16; k++) {
            int idx = tid + k * 256;
            int b = idx >> 6, ii = idx & 63;
            tile[ii][b] = X[((size_t)(t * 64 + b)) * 512 + c * 64 + ii];
        }
        __syncthreads();
#pragma unroll
        for (int k = 0; k < 8; k++) {
            int q = tid + k * 256;
            int ii = q >> 5, b2 = q & 31;
            __half2 v = __floats2half2_rn(tile[ii][2 * b2], tile[ii][2 * b2 + 1]);
            *(__half2*)&g_Xt[((size_t)t * 512 + c * 64 + ii) * HS_STRIDE + 2 * b2] = v;
        }
    }
}

// ===========================================================================
// Fused persistent kernel: per-step X-GEMM (in barrier dead window) +
// recurrence MMA + LSTM cell. fp16 mma.m16n8k16 throughout.
// ===========================================================================
__device__ __forceinline__ float sigmoidf_(float x) {
    return 1.f / (1.f + __expf(-x));
}
__device__ __forceinline__ float tanhf_(float x) {
    float ax = fabsf(x);
    float e  = __expf(-2.f * ax);
    float r  = (1.f - e) / (1.f + e);
    return copysignf(r, x);
}

// X-GEMM over this warp's k-quarter: acc += xs(A, trans) * Ws(B, non-trans)
__device__ __forceinline__ void xgemm_quarter(float (&acc)[2][2][4], uint32_t xs_b,
                                              const __half (*Ws)[WSTR], int ng,
                                              int kb0, int m0, int laneK, int laneM,
                                              int aM, int aK8) {
#pragma unroll
    for (int ks = 0; ks < 8; ks++) {
        const int kb = kb0 + ks * 16;
        uint32_t r0, r1, r2, r3;
        uint32_t baddr = smem_u32(&Ws[16 * ng + aM][kb + aK8]);
        asm volatile(
            "ldmatrix.sync.aligned.m8n8.x4.shared.b16 {%0,%1,%2,%3}, [%4];"
            : "=r"(r0), "=r"(r1), "=r"(r2), "=r"(r3) : "r"(baddr));
#pragma unroll
        for (int mtf = 0; mtf < 2; mtf++) {
            uint32_t aaddr = xs_b + (uint32_t)((kb + laneK) * HS_STRIDE
                                               + m0 + mtf * 16 + laneM) * 2;
            uint32_t a0, a1, a2, a3;
            asm volatile(
                "ldmatrix.sync.aligned.m8n8.x4.trans.shared.b16 {%0,%1,%2,%3}, [%4];"
                : "=r"(a0), "=r"(a1), "=r"(a2), "=r"(a3) : "r"(aaddr));
            asm volatile(
                "mma.sync.aligned.m16n8k16.row.col.f32.f16.f16.f32 "
                "{%0,%1,%2,%3}, {%4,%5,%6,%7}, {%8,%9}, {%0,%1,%2,%3};"
                : "+f"(acc[mtf][0][0]), "+f"(acc[mtf][0][1]),
                  "+f"(acc[mtf][0][2]), "+f"(acc[mtf][0][3])
                : "r"(a0), "r"(a1), "r"(a2), "r"(a3), "r"(r0), "r"(r2));
            asm volatile(
                "mma.sync.aligned.m16n8k16.row.col.f32.f16.f16.f32 "
                "{%0,%1,%2,%3}, {%4,%5,%6,%7}, {%8,%9}, {%0,%1,%2,%3};"
                : "+f"(acc[mtf][1][0]), "+f"(acc[mtf][1][1]),
                  "+f"(acc[mtf][1][2]), "+f"(acc[mtf][1][3])
                : "r"(a0), "r"(a1), "r"(a2), "r"(a3), "r"(r1), "r"(r3));
        }
    }
}

#define DSMEM_BYTES (2 * 512 * HS_STRIDE * 2)   // hs + xs = 147456

__global__ __launch_bounds__(512, 1) void lstm_rec(const float* __restrict__ R,
                                                   const int*   __restrict__ seq,
                                                   const float* __restrict__ h0,
                                                   const float* __restrict__ c0,
                                                   const float* __restrict__ P,
                                                   const float* __restrict__ Bb,
                                                   float* __restrict__ out) {
    extern __shared__ __half dynsm[];
    __half* hs = dynsm;                       // [512][72]
    __half* xs = dynsm + 512 * HS_STRIDE;     // [512][72]
    __shared__ __half Ws[32][WSTR];           // CTA's 32 W rows (fp16)
    __shared__ float accs[4][4][8][65];       // [kg][gate][hl][b]
    __shared__ float cs[8][64], c0s[8][64], h0s[8][64];
    __shared__ float biasg[4][8];
    __shared__ float Ps[3][8];
    __shared__ int   slen[BSZ];

    const int blk = blockIdx.x;
    const int d   = blk >> 6;
    const int hb  = (blk & 63) * 8;
    const int tid = threadIdx.x;
    const int wid = tid >> 5, lane = tid & 31;
    const int grp = lane >> 2, thr = lane & 3;
    const int mg  = wid & 1;
    const int ng  = (wid >> 1) & 1;
    const int kg  = wid >> 2;
    const int m0  = mg * 32;
    const int kb0 = kg * 128;

    unsigned* bar = &g_barD[d][0];
    const uint32_t hs_b = smem_u32(hs);
    const uint32_t xs_b = smem_u32(xs);

    const int seg   = lane >> 3;
    const int laneK = ((seg >> 1) << 3) + (lane & 7);
    const int laneM = (seg & 1) << 3;
    const int aM    = lane & 15;
    const int aK8   = (lane >> 4) << 3;

    const int sgrp   = tid >> 7;
    const int slocal = tid & 127;

    // ---- publish initial h early, then arrive ----
    if (tid < BSZ) slen[tid] = seq[tid];
    {
        int hl = tid >> 6, b = tid & 63;
        size_t idx = ((size_t)d * BSZ + b) * HID + hb + hl;
        float hv = h0[idx], cv = c0[idx];
        h0s[hl][b] = hv; c0s[hl][b] = cv; cs[hl][b] = cv;
        g_h[0][d][hb + hl][b] = __float2half(hv);
    }
    __syncthreads();
    if (tid == 0)
        asm volatile("red.release.gpu.global.add.u32 [%0], 1;" :: "l"(bar) : "memory");

    // ---- R fragments (regs), peephole, bias ----
    uint32_t Rlo[2][8], Rhi[2][8];
#pragma unroll
    for (int nt2 = 0; nt2 < 2; nt2++) {
        const float* Rrow = R + ((size_t)d * NG + (2 * ng + nt2) * 512 + hb + grp) * HID + kb0;
#pragma unroll
        for (int ks = 0; ks < 8; ks++) {
            const int k = ks * 16;
            __half2 lo = __floats2half2_rn(Rrow[k + 2 * thr], Rrow[k + 2 * thr + 1]);
            __half2 hi = __floats2half2_rn(Rrow[k + 2 * thr + 8], Rrow[k + 2 * thr + 9]);
            Rlo[nt2][ks] = *(uint32_t*)&lo;
            Rhi[nt2][ks] = *(uint32_t*)&hi;
        }
    }
    if (tid < 24) {
        int w = tid / 8, hl = tid % 8;
        Ps[w][hl] = P[(size_t)d * 1536 + w * 512 + hb + hl];
    }
    if (tid < 32) {
        int g = tid >> 3, hl = tid & 7;
        biasg[g][hl] = Bb[(size_t)d * 4096 + g * 512 + hb + hl]
                     + Bb[(size_t)d * 4096 + 2048 + g * 512 + hb + hl];
    }

    // ---- Ws load (cp.async) + prologue X(t0) staging ----
#pragma unroll
    for (int k = 0; k < 4; k++) {
        int q = tid + k * 512;
        int w = q >> 6, c16 = q & 63;
        const __half* src = g_Wh + ((size_t)d * NG + (w >> 3) * 512 + hb + (w & 7)) * ID + c16 * 8;
        uint32_t dst = smem_u32(&Ws[w][c16 * 8]);
        asm volatile("cp.async.cg.shared.global [%0], [%1], 16;" :: "r"(dst), "l"(src));
    }
    {
        const int t0 = d ? (SLEN - 1) : 0;
        const char* src = (const char*)&g_Xt[((size_t)t0 * 512 + sgrp * 128) * HS_STRIDE];
        uint32_t    dst = xs_b + (uint32_t)sgrp * CHUNK_BYTES;
#pragma unroll
        for (int i = 0; i < 9; i++) {
            uint32_t off = (uint32_t)(slocal + i * 128) * 16;
            asm volatile("cp.async.cg.shared.global [%0], [%1], 16;"
                         :: "r"(dst + off), "l"(src + off));
        }
    }
    asm volatile("cp.async.commit_group;");
    asm volatile("cp.async.wait_group 0;");
    __syncthreads();

    float acc[2][2][4];
#pragma unroll
    for (int mtf = 0; mtf < 2; mtf++)
#pragma unroll
        for (int nt2 = 0; nt2 < 2; nt2++)
#pragma unroll
            for (int q = 0; q < 4; q++) acc[mtf][nt2][q] = 0.f;

    // Prologue X-GEMM for step 0
    xgemm_quarter(acc, xs_b, Ws, ng, kb0, m0, laneK, laneM, aM, aK8);
    __syncthreads();

    float* Yh = out + 33554432;
    float* Yc = Yh + 65536;

    for (int s = 0; s < SLEN; ++s) {
        const int t   = d ? (SLEN - 1 - s) : s;
        const int cur = s & 1, nxt = cur ^ 1;

        // Issue X staging for next step (independent of barrier)
        if (s < SLEN - 1) {
            const int t2 = d ? (SLEN - 2 - s) : (s + 1);
            const char* src = (const char*)&g_Xt[((size_t)t2 * 512 + sgrp * 128) * HS_STRIDE];
            uint32_t    dst = xs_b + (uint32_t)sgrp * CHUNK_BYTES;
#pragma unroll
            for (int i = 0; i < 9; i++) {
                uint32_t off = (uint32_t)(slocal + i * 128) * 16;
                asm volatile("cp.async.cg.shared.global [%0], [%1], 16;"
                             :: "r"(dst + off), "l"(src + off));
            }
            asm volatile("cp.async.commit_group;");
        }

        // Wait: all producers of h(s)
        if (tid == 0) {
            const unsigned need = (unsigned)NBLKD * (unsigned)(s + 1);
            unsigned v;
            do {
                asm volatile("ld.acquire.gpu.u32 %0, [%1];"
                             : "=r"(v) : "l"(bar) : "memory");
            } while (v < need);
        }
        __syncthreads();

        // Stage own h k-quarter in 2 commit groups
        {
            const char* src = (const char*)&g_h[cur][d][sgrp * 128][0];
            uint32_t    dst = hs_b + (uint32_t)sgrp * CHUNK_BYTES;
#pragma unroll
            for (int i = 0; i < 5; i++) {
                uint32_t off = (uint32_t)(slocal + i * 128) * 16;
                asm volatile("cp.async.cg.shared.global [%0], [%1], 16;"
                             :: "r"(dst + off), "l"(src + off));
            }
            asm volatile("cp.async.commit_group;");
#pragma unroll
            for (int i = 5; i < 9; i++) {
                uint32_t off = (uint32_t)(slocal + i * 128) * 16;
                asm volatile("cp.async.cg.shared.global [%0], [%1], 16;"
                             :: "r"(dst + off), "l"(src + off));
            }
            asm volatile("cp.async.commit_group;");
        }

        asm volatile("cp.async.wait_group 1;");
        asm volatile("bar.sync %0, 128;" :: "r"(1 + sgrp) : "memory");

#pragma unroll
        for (int ks = 0; ks < 4; ks++) {
            const int kb = kb0 + ks * 16 + laneK;
#pragma unroll
            for (int mtf = 0; mtf < 2; mtf++) {
                const int mb = m0 + mtf * 16 + laneM;
                uint32_t addr = hs_b + (uint32_t)(kb * HS_STRIDE + mb) * 2;
                uint32_t a0, a1, a2, a3;
                asm volatile(
                    "ldmatrix.sync.aligned.m8n8.x4.trans.shared.b16 {%0,%1,%2,%3}, [%4];"
                    : "=r"(a0), "=r"(a1), "=r"(a2), "=r"(a3) : "r"(addr));
#pragma unroll
                for (int nt2 = 0; nt2 < 2; nt2++) {
                    asm volatile(
                        "mma.sync.aligned.m16n8k16.row.col.f32.f16.f16.f32 "
                        "{%0,%1,%2,%3}, {%4,%5,%6,%7}, {%8,%9}, {%0,%1,%2,%3};"
                        : "+f"(acc[mtf][nt2][0]), "+f"(acc[mtf][nt2][1]),
                          "+f"(acc[mtf][nt2][2]), "+f"(acc[mtf][nt2][3])
                        : "r"(a0), "r"(a1), "r"(a2), "r"(a3),
                          "r"(Rlo[nt2][ks]), "r"(Rhi[nt2][ks]));
                }
            }
        }

        asm volatile("cp.async.wait_group 0;");
        asm volatile("bar.sync %0, 128;" :: "r"(1 + sgrp) : "memory");

#pragma unroll
        for (int ks = 4; ks < 8; ks++) {
            const int kb = kb0 + ks * 16 + laneK;
#pragma unroll
            for (int mtf = 0; mtf < 2; mtf++) {
                const int mb = m0 + mtf * 16 + laneM;
                uint32_t addr = hs_b + (uint32_t)(kb * HS_STRIDE + mb) * 2;
                uint32_t a0, a1, a2, a3;
                asm volatile(
                    "ldmatrix.sync.aligned.m8n8.x4.trans.shared.b16 {%0,%1,%2,%3}, [%4];"
                    : "=r"(a0), "=r"(a1), "=r"(a2), "=r"(a3) : "r"(addr));
#pragma unroll
                for (int nt2 = 0; nt2 < 2; nt2++) {
                    asm volatile(
                        "mma.sync.aligned.m16n8k16.row.col.f32.f16.f16.f32 "
                        "{%0,%1,%2,%3}, {%4,%5,%6,%7}, {%8,%9}, {%0,%1,%2,%3};"
                        : "+f"(acc[mtf][nt2][0]), "+f"(acc[mtf][nt2][1]),
                          "+f"(acc[mtf][nt2][2]), "+f"(acc[mtf][nt2][3])
                        : "r"(a0), "r"(a1), "r"(a2), "r"(a3),
                          "r"(Rlo[nt2][ks]), "r"(Rhi[nt2][ks]));
                }
            }
        }

        // Exchange: fragments -> accs[kg][gate][hl][b]; then reset acc
#pragma unroll
        for (int mtf = 0; mtf < 2; mtf++) {
            const int m = m0 + mtf * 16 + grp;
#pragma unroll
            for (int nt2 = 0; nt2 < 2; nt2++) {
                const int g = 2 * ng + nt2;
                accs[kg][g][2 * thr]    [m]     = acc[mtf][nt2][0];
                accs[kg][g][2 * thr + 1][m]     = acc[mtf][nt2][1];
                accs[kg][g][2 * thr]    [m + 8] = acc[mtf][nt2][2];
                accs[kg][g][2 * thr + 1][m + 8] = acc[mtf][nt2][3];
            }
        }
#pragma unroll
        for (int mtf = 0; mtf < 2; mtf++)
#pragma unroll
            for (int nt2 = 0; nt2 < 2; nt2++)
#pragma unroll
                for (int q = 0; q < 4; q++) acc[mtf][nt2][q] = 0.f;
        __syncthreads();

        // Elementwise LSTM cell + peephole + mask
        {
            int hl = tid >> 6, b = tid & 63;
            float gi = accs[0][0][hl][b] + accs[1][0][hl][b]
                     + accs[2][0][hl][b] + accs[3][0][hl][b] + biasg[0][hl];
            float go = accs[0][1][hl][b] + accs[1][1][hl][b]
                     + accs[2][1][hl][b] + accs[3][1][hl][b] + biasg[1][hl];
            float gf = accs[0][2][hl][b] + accs[1][2][hl][b]
                     + accs[2][2][hl][b] + accs[3][2][hl][b] + biasg[2][hl];
            float gg = accs[0][3][hl][b] + accs[1][3][hl][b]
                     + accs[2][3][hl][b] + accs[3][3][hl][b] + biasg[3][hl];
            float c  = cs[hl][b];
            float iv = sigmoidf_(gi + Ps[0][hl] * c);
            float fv = sigmoidf_(gf + Ps[1][hl] * c);
            float ct = tanhf_(gg);
            float cn = fv * c + iv * ct;
            float ov = sigmoidf_(go + Ps[2][hl] * cn);
            float hn = ov * tanhf_(cn);
            if (t >= slen[b]) { hn = h0s[hl][b]; cn = c0s[hl][b]; }
            cs[hl][b] = cn;
            g_h[nxt][d][hb + hl][b] = __float2half(hn);
            out[(((size_t)t * 2 + d) * BSZ + b) * HID + hb + hl] = hn;
            if (s == SLEN - 1) {
                size_t fi = ((size_t)d * BSZ + b) * HID + hb + hl;
                Yh[fi] = hn;
                Yc[fi] = cn;
            }
        }
        __syncthreads();
        if (tid == 0)
            asm volatile("red.release.gpu.global.add.u32 [%0], 1;" :: "l"(bar) : "memory");

        // X-GEMM for next step in the dead window (xs already resident)
        if (s < SLEN - 1) {
            xgemm_quarter(acc, xs_b, Ws, ng, kb0, m0, laneK, laneM, aM, aK8);
            asm volatile("bar.sync %0, 128;" :: "r"(1 + sgrp) : "memory");
        }
    }
}

// ---------------------------------------------------------------------------
extern "C" void kernel_launch(void* const* d_in, const int* in_sizes, int n_in,
                              void* d_out, int out_size) {
    const float* X   = (const float*)d_in[0];
    const float* W   = (const float*)d_in[1];
    const float* R   = (const float*)d_in[2];
    const float* Bb  = (const float*)d_in[3];
    const int*   sl  = (const int*)  d_in[4];
    const float* h0  = (const float*)d_in[5];
    const float* c0  = (const float*)d_in[6];
    const float* P   = (const float*)d_in[7];
    float* out = (float*)d_out;

    static int configured = 0;
    if (!configured) {
        cudaFuncSetAttribute(lstm_rec, cudaFuncAttributeMaxDynamicSharedMemorySize,
                             DSMEM_BYTES);
        configured = 1;
    }

    convert_w<<<2048, 256>>>(W);
    convert_xt<<<512, 256>>>(X);
    lstm_rec<<<NBLK, 512, DSMEM_BYTES>>>(R, sl, h0, c0, P, Bb, out);
}